// round 16
// baseline (speedup 1.0000x reference)
#include <cuda_runtime.h>
#include <cuda_fp16.h>
#include <math.h>
#include <stdint.h>

#define B_   64
#define T_   2000
#define E_   512
#define D_   1024
#define A_   128
#define PAD_ 15
#define TTILE  64
#define NTILES 32          // ceil(2000/64)

// ---- device scratch (allocation-free rule) ----
__device__ __align__(16) float  g_pq[B_ * A_];
__device__ __align__(16) float  g_scores[B_ * T_];
__device__ __align__(16) float  g_cpart[B_ * NTILES * E_];
__device__ __align__(16) float2 g_mtl[B_ * NTILES];
__device__ __align__(16) __half g_WmH[A_ * E_], g_WmL[A_ * E_];
__device__ __align__(16) __half g_WlocH[A_ * 64], g_WlocL[A_ * 64];
__device__ unsigned g_cnt[B_];   // zero-init; reset by last CTA each run

// ---- smem layout (bytes) ----
#define S_AW   0            // 2 x 96 floats = 768
#define S_PQ   768          // 128 floats
#define S_V    1280         // 128 floats
#define S_SC   1792         // 2 x 64 floats = 512
#define S_FIN  2304         // 64 floats
#define S_W    2560         // 64 floats
#define OFF_B  2816         // 2 bufs x 32768 (BH 16384 | BL 16384)
#define SMEM_TOTAL (OFF_B + 65536)   // 68352 -> 3 CTAs/SM

// ---------------- PTX helpers ----------------
__device__ __forceinline__ uint32_t smem_u32(const void* p) {
    uint32_t a;
    asm("{ .reg .u64 t; cvta.to.shared.u64 t, %1; cvt.u32.u64 %0, t; }"
        : "=r"(a) : "l"(p));
    return a;
}
__device__ __forceinline__ void cp16(uint32_t dst, const void* src) {
    asm volatile("cp.async.cg.shared.global [%0], [%1], 16;"
                 :: "r"(dst), "l"(src) : "memory");
}
__device__ __forceinline__ void cp_commit() {
    asm volatile("cp.async.commit_group;" ::: "memory");
}
__device__ __forceinline__ void cp_wait0() {
    asm volatile("cp.async.wait_group 0;" ::: "memory");
}
#define LDSM4(R, addr)                                                        \
    asm volatile("ldmatrix.sync.aligned.m8n8.x4.shared.b16 {%0,%1,%2,%3}, [%4];" \
                 : "=r"((R)[0]), "=r"((R)[1]), "=r"((R)[2]), "=r"((R)[3])     \
                 : "r"(addr))
#define MMA16816(acc, Af, b0, b1)                                             \
    asm volatile("mma.sync.aligned.m16n8k16.row.col.f32.f16.f16.f32 "         \
                 "{%0,%1,%2,%3},{%4,%5,%6,%7},{%8,%9},{%0,%1,%2,%3};"         \
                 : "+f"((acc)[0]), "+f"((acc)[1]), "+f"((acc)[2]), "+f"((acc)[3]) \
                 : "r"((Af)[0]), "r"((Af)[1]), "r"((Af)[2]), "r"((Af)[3]),    \
                   "r"(b0), "r"(b1))

// fp32 pair -> fp16 hi/lo planes (bit-identical to scalar RN sequence)
__device__ __forceinline__ void split2(float x, float y,
                                       uint32_t& hi, uint32_t& lo) {
    uint32_t h;
    asm("cvt.rn.f16x2.f32 %0, %1, %2;" : "=r"(h) : "f"(y), "f"(x));
    float fx, fy;
    asm("{\n\t.reg .b16 a, b;\n\t"
        "mov.b32 {a, b}, %2;\n\t"
        "cvt.f32.f16 %0, a;\n\t"
        "cvt.f32.f16 %1, b;\n\t}"
        : "=f"(fx), "=f"(fy) : "r"(h));
    float lx = x - fx, ly = y - fy;
    uint32_t l;
    asm("cvt.rn.f16x2.f32 %0, %1, %2;" : "=r"(l) : "f"(ly), "f"(lx));
    hi = h;
    lo = l;
}

// ---------------------------------------------------------------------------
// merged prep (Wm/Wloc fp16 split) + pq GEMV (warp-per-row, q in registers)
// grid 320 x 512: blocks 0..63 -> prep (1024 elems), 64..319 -> pq (4/batch)
// ---------------------------------------------------------------------------
__global__ void __launch_bounds__(512)
prep_pq_kernel(const float* __restrict__ Wm,
               const float* __restrict__ Wloc,
               const float* __restrict__ query,
               const float* __restrict__ Wq) {
    int tid = threadIdx.x;
    if (blockIdx.x < 64) {
        #pragma unroll
        for (int rep = 0; rep < 2; ++rep) {
            int idx = blockIdx.x * 1024 + rep * 512 + tid;   // 65536 total
            float x = Wm[idx];
            __half h = __float2half_rn(x);
            __half l = __float2half_rn(x - __half2float(h));
            g_WmH[idx] = h;
            g_WmL[idx] = l;
            if (idx < A_ * 64) {
                int j = idx & 63;
                float w = (j < 62) ? Wloc[(idx >> 6) * 62 + j] : 0.f;
                __half wh = __float2half_rn(w);
                __half wl = __float2half_rn(w - __half2float(wh));
                g_WlocH[idx] = wh;
                g_WlocL[idx] = wl;
            }
        }
    } else {
        int p = blockIdx.x - 64;
        int b = p >> 2, qd = p & 3;              // 4 blocks per batch
        int wid = tid >> 5, lane = tid & 31;     // 16 warps, 2 rows each
        const float4* q4 = (const float4*)(query + (size_t)b * D_);
        float4 qv[8];
        #pragma unroll
        for (int j = 0; j < 8; ++j) qv[j] = q4[lane + j * 32];
        int a0 = qd * 32 + wid * 2;
        const float4* w40 = (const float4*)(Wq + (size_t)a0 * D_);
        const float4* w41 = (const float4*)(Wq + (size_t)(a0 + 1) * D_);
        float4 wv0[8], wv1[8];
        #pragma unroll
        for (int j = 0; j < 8; ++j) wv0[j] = w40[lane + j * 32];
        #pragma unroll
        for (int j = 0; j < 8; ++j) wv1[j] = w41[lane + j * 32];
        float s0 = 0.f, s1 = 0.f;
        #pragma unroll
        for (int j = 0; j < 8; ++j) {
            s0 += qv[j].x * wv0[j].x + qv[j].y * wv0[j].y +
                  qv[j].z * wv0[j].z + qv[j].w * wv0[j].w;
            s1 += qv[j].x * wv1[j].x + qv[j].y * wv1[j].y +
                  qv[j].z * wv1[j].z + qv[j].w * wv1[j].w;
        }
        #pragma unroll
        for (int off = 16; off; off >>= 1) {
            s0 += __shfl_xor_sync(0xffffffffu, s0, off);
            s1 += __shfl_xor_sync(0xffffffffu, s1, off);
        }
        if (lane == 0) {
            g_pq[b * A_ + a0] = s0;
            g_pq[b * A_ + a0 + 1] = s1;
        }
    }
}

// ---------------------------------------------------------------------------
// one k-step: LDSM B frags + 48 MMAs (hh, hl, lh)
// ---------------------------------------------------------------------------
__device__ __forceinline__ void mma_step(
    float (&acc)[2][8][4], const uint32_t* ah, const uint32_t* al,
    uint32_t curB, int ks, const uint32_t (&bRowB)[4],
    uint32_t bCk, uint32_t rx) {
    uint32_t bh[4][4], bl[4][4];
    #pragma unroll
    for (int g4 = 0; g4 < 4; ++g4) {
        uint32_t bd = curB + bRowB[g4] +
                      ((((uint32_t)(2 * ks) + bCk) ^ rx) << 4);
        LDSM4(bh[g4], bd);
        LDSM4(bl[g4], bd + 16384);
    }
    #pragma unroll
    for (int m = 0; m < 2; ++m)
        #pragma unroll
        for (int g4 = 0; g4 < 4; ++g4) {
            MMA16816(acc[m][2 * g4],     ah + 4 * m, bh[g4][0], bh[g4][1]);
            MMA16816(acc[m][2 * g4 + 1], ah + 4 * m, bh[g4][2], bh[g4][3]);
        }
    #pragma unroll
    for (int m = 0; m < 2; ++m)
        #pragma unroll
        for (int g4 = 0; g4 < 4; ++g4) {
            MMA16816(acc[m][2 * g4],     ah + 4 * m, bl[g4][0], bl[g4][1]);
            MMA16816(acc[m][2 * g4 + 1], ah + 4 * m, bl[g4][2], bl[g4][3]);
        }
    #pragma unroll
    for (int m = 0; m < 2; ++m)
        #pragma unroll
        for (int g4 = 0; g4 < 4; ++g4) {
            MMA16816(acc[m][2 * g4],     al + 4 * m, bh[g4][0], bh[g4][1]);
            MMA16816(acc[m][2 * g4 + 1], al + 4 * m, bh[g4][2], bh[g4][3]);
        }
}

// ---------------------------------------------------------------------------
// fused: scores (fp16-split HMMA, A direct-from-global) + tile softmax
// partial + ctx partial + LAST-CTA-per-batch combine. 3 CTAs/SM.
// ---------------------------------------------------------------------------
__global__ void __launch_bounds__(128, 3)
scores_fused_kernel(const float* __restrict__ memory,
                    const float* __restrict__ aw,
                    const float* __restrict__ v,
                    float* __restrict__ ctx_out,
                    float* __restrict__ align_out) {
    extern __shared__ unsigned char smem[];
    __shared__ unsigned sLast;
    __shared__ float fac2[NTILES];
    __shared__ float sM2[2];
    const uint32_t sb = smem_u32(smem);
    const int tid = threadIdx.x;
    const int wid = tid >> 5, lid = tid & 31;
    const int b = blockIdx.y;
    const int tile = blockIdx.x;
    const int t0 = tile * TTILE;

    float* sAw  = (float*)(smem + S_AW);     // [2][96]
    float* sPQ  = (float*)(smem + S_PQ);
    float* sV   = (float*)(smem + S_V);
    float* sSc  = (float*)(smem + S_SC);     // [2][64]
    float* sFin = (float*)(smem + S_FIN);    // [64]
    float* sW   = (float*)(smem + S_W);      // [64]

    const int warpT = wid >> 1, warpA = wid & 1;
    const int tBase = warpT * 32;
    const int aBase = warpA * 64;

    const int bRowOff = (lid & 7) + (lid >> 4) * 8;
    const uint32_t bCk = (uint32_t)((lid >> 3) & 1);
    const uint32_t rx = (uint32_t)(lid & 7);

    const int g = lid >> 2;          // row within 8
    const int cq = (lid & 3) * 2;    // col pair base

    for (int i = tid; i < TTILE + 2 * PAD_; i += 128) {
        int tg = t0 - PAD_ + i;
        float c0 = 0.f, c1 = 0.f;
        if (tg >= 0 && tg < T_) {
            const float* p = aw + ((size_t)b * T_ + tg) * 2;
            c0 = p[0]; c1 = p[1];
        }
        sAw[i] = c0;
        sAw[96 + i] = c1;
    }
    sPQ[tid] = g_pq[b * A_ + tid];
    sV[tid] = v[tid];

    // prologue: Wloc (conv B) into buf0
    #pragma unroll
    for (int it = 0; it < 8; ++it) {
        int idx = it * 128 + tid;
        uint32_t row = (uint32_t)(idx >> 3), q = (uint32_t)(idx & 7);
        uint32_t dst = sb + OFF_B + (row << 7) + (((q ^ row) & 7u) << 4);
        cp16(dst, g_WlocH + row * 64 + q * 8);
        cp16(dst + 16384, g_WlocL + row * 64 + q * 8);
    }
    cp_commit();
    cp_wait0();
    __syncthreads();

    const float* pb = memory +
        ((size_t)b * T_ + (size_t)(t0 + tBase + g)) * E_ + cq;
    bool vr[4];
    #pragma unroll
    for (int j = 0; j < 4; ++j) vr[j] = (t0 + tBase + g + 8 * j) < T_;

    float2 f[8];
    #pragma unroll
    for (int i = 0; i < 8; ++i) {
        int ri = ((i >> 2) << 1) | (i & 1);
        const float* p = pb + (size_t)(8 * ri) * E_ + (((i >> 1) & 1) << 3);
        f[i] = vr[ri] ? *(const float2*)p : make_float2(0.f, 0.f);
    }

    float acc[2][8][4];
    #pragma unroll
    for (int m = 0; m < 2; ++m)
        #pragma unroll
        for (int n = 0; n < 8; ++n)
            #pragma unroll
            for (int e = 0; e < 4; ++e) acc[m][n][e] = 0.f;

    uint32_t bRowB[4];
    #pragma unroll
    for (int g4 = 0; g4 < 4; ++g4)
        bRowB[g4] = (uint32_t)(aBase + g4 * 16 + bRowOff) << 7;

    // ---- conv chunk (c=0): A frags from sAw, B in buf0 ----
    {
        #pragma unroll
        for (int it = 0; it < 8; ++it) {
            int idx = it * 128 + tid;
            uint32_t row = (uint32_t)(idx >> 3), q = (uint32_t)(idx & 7);
            uint32_t dst = sb + OFF_B + 32768 +
                           (row << 7) + (((q ^ row) & 7u) << 4);
            cp16(dst, g_WmH + (size_t)row * E_ + q * 8);
            cp16(dst + 16384, g_WmL + (size_t)row * E_ + q * 8);
        }
        cp_commit();
        const uint32_t curB = sb + OFF_B;
        #pragma unroll
        for (int ks = 0; ks < 4; ++ks) {
            uint32_t ah[8], al[8];
            #pragma unroll
            for (int i = 0; i < 8; ++i) {
                int r = tBase + ((i >> 2) << 4) + g + ((i & 1) << 3);
                int j0 = (ks << 4) + cq + (((i >> 1) & 1) << 3);
                float x0 = 0.f, x1 = 0.f;
                if (j0 < 62) {
                    int cj = j0 >= 31;
                    x0 = sAw[cj * 96 + r + (j0 - cj * 31)];
                }
                if (j0 + 1 < 62) {
                    int cj = (j0 + 1) >= 31;
                    x1 = sAw[cj * 96 + r + (j0 + 1 - cj * 31)];
                }
                split2(x0, x1, ah[i], al[i]);
            }
            mma_step(acc, ah, al, curB, ks, bRowB, bCk, rx);
        }
        cp_wait0();
        __syncthreads();
    }

    // ---- memory chunks c = 1..8 ----
    for (int c = 1; c <= 8; ++c) {
        const uint32_t curB = sb + OFF_B + (uint32_t)(c & 1) * 32768;
        if (c < 8) {
            const __half* WH = g_WmH + c * 64;
            const __half* WL = g_WmL + c * 64;
            uint32_t nxtB = sb + OFF_B + (uint32_t)((c + 1) & 1) * 32768;
            #pragma unroll
            for (int it = 0; it < 8; ++it) {
                int idx = it * 128 + tid;
                uint32_t row = (uint32_t)(idx >> 3), q = (uint32_t)(idx & 7);
                uint32_t dst = nxtB + (row << 7) + (((q ^ row) & 7u) << 4);
                cp16(dst, WH + (size_t)row * E_ + q * 8);
                cp16(dst + 16384, WL + (size_t)row * E_ + q * 8);
            }
            cp_commit();
        }
        #pragma unroll
        for (int ks = 0; ks < 4; ++ks) {
            int s = (c - 1) * 4 + ks;
            float2 fn[8];
            bool more = s < 31;
            const float* pc = pb + (size_t)(s + 1) * 16;
            #pragma unroll
            for (int i = 0; i < 8; ++i) {
                int ri = ((i >> 2) << 1) | (i & 1);
                const float* p = pc + (size_t)(8 * ri) * E_ +
                                 (((i >> 1) & 1) << 3);
                fn[i] = (more && vr[ri]) ? *(const float2*)p
                                         : make_float2(0.f, 0.f);
            }
            uint32_t ah[8], al[8];
            #pragma unroll
            for (int i = 0; i < 8; ++i)
                split2(f[i].x, f[i].y, ah[i], al[i]);
            mma_step(acc, ah, al, curB, ks, bRowB, bCk, rx);
            #pragma unroll
            for (int i = 0; i < 8; ++i) f[i] = fn[i];
        }
        if (c < 8) cp_wait0();
        __syncthreads();
    }

    // ---- scores: s[t] = sum_a v[a]*tanh(acc + pq[a]) ----
    {
        float s[4] = {0.f, 0.f, 0.f, 0.f};
        #pragma unroll
        for (int m = 0; m < 2; ++m) {
            #pragma unroll
            for (int n = 0; n < 8; ++n) {
                int a0 = aBase + n * 8 + (lid & 3) * 2;
                float v0 = sV[a0], v1 = sV[a0 + 1];
                float q0 = sPQ[a0], q1 = sPQ[a0 + 1];
                s[2 * m]     += v0 * tanhf(acc[m][n][0] + q0)
                              + v1 * tanhf(acc[m][n][1] + q1);
                s[2 * m + 1] += v0 * tanhf(acc[m][n][2] + q0)
                              + v1 * tanhf(acc[m][n][3] + q1);
            }
        }
        #pragma unroll
        for (int off = 1; off < 4; off <<= 1) {
            #pragma unroll
            for (int i = 0; i < 4; ++i)
                s[i] += __shfl_xor_sync(0xffffffffu, s[i], off);
        }
        if ((lid & 3) == 0) {
            int r = tBase + (lid >> 2);
            sSc[warpA * 64 + r]      = s[0];
            sSc[warpA * 64 + r + 8]  = s[1];
            sSc[warpA * 64 + r + 16] = s[2];
            sSc[warpA * 64 + r + 24] = s[3];
        }
    }
    __syncthreads();

    // ---- tile softmax partial ----
    if (tid < TTILE) {
        int gt = t0 + tid;
        float sf = sSc[tid] + sSc[64 + tid];
        bool valid = gt < T_;
        if (valid) g_scores[b * T_ + gt] = sf;
        sFin[tid] = valid ? sf : -1e30f;
    }
    __syncthreads();
    if (wid == 0) {
        float s0 = sFin[lid], s1 = sFin[lid + 32];
        float m = fmaxf(s0, s1);
        #pragma unroll
        for (int off = 16; off; off >>= 1)
            m = fmaxf(m, __shfl_xor_sync(0xffffffffu, m, off));
        float w0 = __expf(s0 - m), w1 = __expf(s1 - m);
        float l = w0 + w1;
        #pragma unroll
        for (int off = 16; off; off >>= 1)
            l += __shfl_xor_sync(0xffffffffu, l, off);
        sW[lid] = w0;
        sW[lid + 32] = w1;
        if (lid == 0) g_mtl[b * NTILES + tile] = make_float2(m, l);
    }
    __syncthreads();

    // ---- ctx partial: cpart[e] = sum_t w[t] * memory[b, t0+t, e] ----
    {
        const int tmax = min(TTILE, T_ - t0);
        const float* mrow = memory + ((size_t)b * T_ + t0) * E_ + tid * 4;
        float4 acc0 = make_float4(0.f, 0.f, 0.f, 0.f);
        float4 acc1 = make_float4(0.f, 0.f, 0.f, 0.f);
        int t = 0;
        for (; t + 2 <= tmax; t += 2) {
            float w0 = sW[t], w1 = sW[t + 1];
            float4 m0 = *(const float4*)(mrow);
            float4 m1 = *(const float4*)(mrow + E_);
            mrow += 2 * E_;
            acc0.x += w0 * m0.x; acc0.y += w0 * m0.y;
            acc0.z += w0 * m0.z; acc0.w += w0 * m0.w;
            acc1.x += w1 * m1.x; acc1.y += w1 * m1.y;
            acc1.z += w1 * m1.z; acc1.w += w1 * m1.w;
        }
        if (t < tmax) {
            float w0 = sW[t];
            float4 m0 = *(const float4*)(mrow);
            acc0.x += w0 * m0.x; acc0.y += w0 * m0.y;
            acc0.z += w0 * m0.z; acc0.w += w0 * m0.w;
        }
        acc0.x += acc1.x; acc0.y += acc1.y;
        acc0.z += acc1.z; acc0.w += acc1.w;
        *((float4*)(g_cpart + ((size_t)b * NTILES + tile) * E_) + tid) = acc0;
    }

    // ---- last CTA of this batch performs the combine ----
    __threadfence();
    __syncthreads();
    if (tid == 0) sLast = atomicAdd(&g_cnt[b], 1u);
    __syncthreads();
    if (sLast == NTILES - 1) {
        if (wid == 0) {
            float2 ml = g_mtl[b * NTILES + lid];
            float M = ml.x;
            #pragma unroll
            for (int off = 16; off; off >>= 1)
                M = fmaxf(M, __shfl_xor_sync(0xffffffffu, M, off));
            float fv = __expf(ml.x - M);
            float L = ml.y * fv;
            #pragma unroll
            for (int off = 16; off; off >>= 1)
                L += __shfl_xor_sync(0xffffffffu, L, off);
            fac2[lid] = fv;
            if (lid == 0) { sM2[0] = M; sM2[1] = L; }
        }
        __syncthreads();
        float M = sM2[0];
        float invL = 1.f / sM2[1];
        // context: 512 floats, 128 threads x float4
        {
            float4 s4 = make_float4(0.f, 0.f, 0.f, 0.f);
            const float4* cp4 = (const float4*)(g_cpart +
                                (size_t)b * NTILES * E_) + tid;
            #pragma unroll
            for (int i = 0; i < NTILES; ++i) {
                float4 c = cp4[i * (E_ / 4)];
                float fv = fac2[i];
                s4.x += c.x * fv; s4.y += c.y * fv;
                s4.z += c.z * fv; s4.w += c.w * fv;
            }
            s4.x *= invL; s4.y *= invL; s4.z *= invL; s4.w *= invL;
            *((float4*)(ctx_out + b * E_) + tid) = s4;
        }
        // alignments
        for (int t = tid; t < T_; t += 128)
            align_out[b * T_ + t] = __expf(g_scores[b * T_ + t] - M) * invL;
        if (tid == 0) g_cnt[b] = 0;   // reset for next graph replay
    }
}

// ---------------------------------------------------------------------------
extern "C" void kernel_launch(void* const* d_in, const int* in_sizes, int n_in,
                              void* d_out, int out_size) {
    const float* query  = (const float*)d_in[0];  // [64,1024]
    const float* memory = (const float*)d_in[1];  // [64,2000,512]
    const float* aw     = (const float*)d_in[2];  // [64,2000,2]
    const float* Wq     = (const float*)d_in[3];  // [128,1024]
    const float* Wm     = (const float*)d_in[4];  // [128,512]
    const float* Wloc   = (const float*)d_in[5];  // [128,2,31]
    const float* v      = (const float*)d_in[6];  // [128]

    float* ctx = (float*)d_out;                   // [64,512]
    float* aligns = ctx + B_ * E_;                // [64,2000]

    cudaFuncSetAttribute(scores_fused_kernel,
                         cudaFuncAttributeMaxDynamicSharedMemorySize, SMEM_TOTAL);

    prep_pq_kernel<<<320, 512>>>(Wm, Wloc, query, Wq);
    scores_fused_kernel<<<dim3(NTILES, B_), 128, SMEM_TOTAL>>>(
        memory, aw, v, ctx, aligns);
}

// round 17
// speedup vs baseline: 1.1673x; 1.1673x over previous
#include <cuda_runtime.h>
#include <cuda_fp16.h>
#include <math.h>
#include <stdint.h>

#define B_   64
#define T_   2000
#define E_   512
#define D_   1024
#define A_   128
#define PAD_ 15
#define TTILE  64
#define NTILES 32          // ceil(2000/64)

// ---- device scratch (allocation-free rule) ----
__device__ __align__(16) float  g_pq[B_ * A_];
__device__ __align__(16) float  g_scores[B_ * T_];
__device__ __align__(16) float  g_cpart[B_ * NTILES * E_];
__device__ __align__(16) float2 g_mtl[B_ * NTILES];
__device__ __align__(16) __half g_WmH[A_ * E_], g_WmL[A_ * E_];
__device__ __align__(16) __half g_WlocH[A_ * 64], g_WlocL[A_ * 64];

// ---- smem layout (bytes) ----
#define S_AW   0            // 2 x 96 floats = 768
#define S_PQ   768          // 128 floats
#define S_V    1280         // 128 floats
#define S_SC   1792         // 2 x 64 floats = 512
#define S_FIN  2304         // 64 floats
#define S_W    2560         // 64 floats
#define OFF_B  2816         // 2 bufs x 32768 (BH 16384 | BL 16384)
#define SMEM_TOTAL (OFF_B + 65536)   // 68352 -> 3 CTAs/SM

// ---------------- PTX helpers ----------------
__device__ __forceinline__ uint32_t smem_u32(const void* p) {
    uint32_t a;
    asm("{ .reg .u64 t; cvta.to.shared.u64 t, %1; cvt.u32.u64 %0, t; }"
        : "=r"(a) : "l"(p));
    return a;
}
__device__ __forceinline__ void cp16(uint32_t dst, const void* src) {
    asm volatile("cp.async.cg.shared.global [%0], [%1], 16;"
                 :: "r"(dst), "l"(src) : "memory");
}
__device__ __forceinline__ void cp_commit() {
    asm volatile("cp.async.commit_group;" ::: "memory");
}
__device__ __forceinline__ void cp_wait0() {
    asm volatile("cp.async.wait_group 0;" ::: "memory");
}
#define LDSM4(R, addr)                                                        \
    asm volatile("ldmatrix.sync.aligned.m8n8.x4.shared.b16 {%0,%1,%2,%3}, [%4];" \
                 : "=r"((R)[0]), "=r"((R)[1]), "=r"((R)[2]), "=r"((R)[3])     \
                 : "r"(addr))
#define MMA16816(acc, Af, b0, b1)                                             \
    asm volatile("mma.sync.aligned.m16n8k16.row.col.f32.f16.f16.f32 "         \
                 "{%0,%1,%2,%3},{%4,%5,%6,%7},{%8,%9},{%0,%1,%2,%3};"         \
                 : "+f"((acc)[0]), "+f"((acc)[1]), "+f"((acc)[2]), "+f"((acc)[3]) \
                 : "r"((Af)[0]), "r"((Af)[1]), "r"((Af)[2]), "r"((Af)[3]),    \
                   "r"(b0), "r"(b1))

// fp32 pair -> fp16 hi/lo planes (bit-identical to scalar RN sequence)
__device__ __forceinline__ void split2(float x, float y,
                                       uint32_t& hi, uint32_t& lo) {
    uint32_t h;
    asm("cvt.rn.f16x2.f32 %0, %1, %2;" : "=r"(h) : "f"(y), "f"(x));
    float fx, fy;
    asm("{\n\t.reg .b16 a, b;\n\t"
        "mov.b32 {a, b}, %2;\n\t"
        "cvt.f32.f16 %0, a;\n\t"
        "cvt.f32.f16 %1, b;\n\t}"
        : "=f"(fx), "=f"(fy) : "r"(h));
    float lx = x - fx, ly = y - fy;
    uint32_t l;
    asm("cvt.rn.f16x2.f32 %0, %1, %2;" : "=r"(l) : "f"(ly), "f"(lx));
    hi = h;
    lo = l;
}

// ---------------------------------------------------------------------------
// merged prep (Wm/Wloc fp16 split) + pq GEMV (warp-per-row, q in registers)
// grid 320 x 512: blocks 0..63 -> prep (1024 elems), 64..319 -> pq (4/batch)
// ---------------------------------------------------------------------------
__global__ void __launch_bounds__(512)
prep_pq_kernel(const float* __restrict__ Wm,
               const float* __restrict__ Wloc,
               const float* __restrict__ query,
               const float* __restrict__ Wq) {
    int tid = threadIdx.x;
    if (blockIdx.x < 64) {
        #pragma unroll
        for (int rep = 0; rep < 2; ++rep) {
            int idx = blockIdx.x * 1024 + rep * 512 + tid;   // 65536 total
            float x = Wm[idx];
            __half h = __float2half_rn(x);
            __half l = __float2half_rn(x - __half2float(h));
            g_WmH[idx] = h;
            g_WmL[idx] = l;
            if (idx < A_ * 64) {
                int j = idx & 63;
                float w = (j < 62) ? Wloc[(idx >> 6) * 62 + j] : 0.f;
                __half wh = __float2half_rn(w);
                __half wl = __float2half_rn(w - __half2float(wh));
                g_WlocH[idx] = wh;
                g_WlocL[idx] = wl;
            }
        }
    } else {
        int p = blockIdx.x - 64;
        int b = p >> 2, qd = p & 3;              // 4 blocks per batch
        int wid = tid >> 5, lane = tid & 31;     // 16 warps, 2 rows each
        const float4* q4 = (const float4*)(query + (size_t)b * D_);
        float4 qv[8];
        #pragma unroll
        for (int j = 0; j < 8; ++j) qv[j] = q4[lane + j * 32];
        int a0 = qd * 32 + wid * 2;
        const float4* w40 = (const float4*)(Wq + (size_t)a0 * D_);
        const float4* w41 = (const float4*)(Wq + (size_t)(a0 + 1) * D_);
        float4 wv0[8], wv1[8];
        #pragma unroll
        for (int j = 0; j < 8; ++j) wv0[j] = w40[lane + j * 32];
        #pragma unroll
        for (int j = 0; j < 8; ++j) wv1[j] = w41[lane + j * 32];
        float s0 = 0.f, s1 = 0.f;
        #pragma unroll
        for (int j = 0; j < 8; ++j) {
            s0 += qv[j].x * wv0[j].x + qv[j].y * wv0[j].y +
                  qv[j].z * wv0[j].z + qv[j].w * wv0[j].w;
            s1 += qv[j].x * wv1[j].x + qv[j].y * wv1[j].y +
                  qv[j].z * wv1[j].z + qv[j].w * wv1[j].w;
        }
        #pragma unroll
        for (int off = 16; off; off >>= 1) {
            s0 += __shfl_xor_sync(0xffffffffu, s0, off);
            s1 += __shfl_xor_sync(0xffffffffu, s1, off);
        }
        if (lane == 0) {
            g_pq[b * A_ + a0] = s0;
            g_pq[b * A_ + a0 + 1] = s1;
        }
    }
}

// ---------------------------------------------------------------------------
// one k-step: LDSM B frags + 48 MMAs (hh, hl, lh)
// ---------------------------------------------------------------------------
__device__ __forceinline__ void mma_step(
    float (&acc)[2][8][4], const uint32_t* ah, const uint32_t* al,
    uint32_t curB, int ks, const uint32_t (&bRowB)[4],
    uint32_t bCk, uint32_t rx) {
    uint32_t bh[4][4], bl[4][4];
    #pragma unroll
    for (int g4 = 0; g4 < 4; ++g4) {
        uint32_t bd = curB + bRowB[g4] +
                      ((((uint32_t)(2 * ks) + bCk) ^ rx) << 4);
        LDSM4(bh[g4], bd);
        LDSM4(bl[g4], bd + 16384);
    }
    #pragma unroll
    for (int m = 0; m < 2; ++m)
        #pragma unroll
        for (int g4 = 0; g4 < 4; ++g4) {
            MMA16816(acc[m][2 * g4],     ah + 4 * m, bh[g4][0], bh[g4][1]);
            MMA16816(acc[m][2 * g4 + 1], ah + 4 * m, bh[g4][2], bh[g4][3]);
        }
    #pragma unroll
    for (int m = 0; m < 2; ++m)
        #pragma unroll
        for (int g4 = 0; g4 < 4; ++g4) {
            MMA16816(acc[m][2 * g4],     ah + 4 * m, bl[g4][0], bl[g4][1]);
            MMA16816(acc[m][2 * g4 + 1], ah + 4 * m, bl[g4][2], bl[g4][3]);
        }
    #pragma unroll
    for (int m = 0; m < 2; ++m)
        #pragma unroll
        for (int g4 = 0; g4 < 4; ++g4) {
            MMA16816(acc[m][2 * g4],     al + 4 * m, bh[g4][0], bh[g4][1]);
            MMA16816(acc[m][2 * g4 + 1], al + 4 * m, bh[g4][2], bh[g4][3]);
        }
}

// ---------------------------------------------------------------------------
// fused: scores (fp16-split HMMA, A direct-from-global fragments) +
//        tile softmax partial + ctx partial. 64t x 128a, 128 thr, 3 CTAs/SM.
// (round-15 configuration — best measured)
// ---------------------------------------------------------------------------
__global__ void __launch_bounds__(128, 3)
scores_fused_kernel(const float* __restrict__ memory,
                    const float* __restrict__ aw,
                    const float* __restrict__ v) {
    extern __shared__ unsigned char smem[];
    const uint32_t sb = smem_u32(smem);
    const int tid = threadIdx.x;
    const int wid = tid >> 5, lid = tid & 31;
    const int b = blockIdx.y;
    const int tile = blockIdx.x;
    const int t0 = tile * TTILE;

    float* sAw  = (float*)(smem + S_AW);     // [2][96]
    float* sPQ  = (float*)(smem + S_PQ);
    float* sV   = (float*)(smem + S_V);
    float* sSc  = (float*)(smem + S_SC);     // [2][64]
    float* sFin = (float*)(smem + S_FIN);    // [64]
    float* sW   = (float*)(smem + S_W);      // [64]

    const int warpT = wid >> 1, warpA = wid & 1;
    const int tBase = warpT * 32;
    const int aBase = warpA * 64;

    const int bRowOff = (lid & 7) + (lid >> 4) * 8;
    const uint32_t bCk = (uint32_t)((lid >> 3) & 1);
    const uint32_t rx = (uint32_t)(lid & 7);

    const int g = lid >> 2;          // row within 8
    const int cq = (lid & 3) * 2;    // col pair base

    for (int i = tid; i < TTILE + 2 * PAD_; i += 128) {
        int tg = t0 - PAD_ + i;
        float c0 = 0.f, c1 = 0.f;
        if (tg >= 0 && tg < T_) {
            const float* p = aw + ((size_t)b * T_ + tg) * 2;
            c0 = p[0]; c1 = p[1];
        }
        sAw[i] = c0;
        sAw[96 + i] = c1;
    }
    sPQ[tid] = g_pq[b * A_ + tid];
    sV[tid] = v[tid];

    // prologue: Wloc (conv B) into buf0
    #pragma unroll
    for (int it = 0; it < 8; ++it) {
        int idx = it * 128 + tid;
        uint32_t row = (uint32_t)(idx >> 3), q = (uint32_t)(idx & 7);
        uint32_t dst = sb + OFF_B + (row << 7) + (((q ^ row) & 7u) << 4);
        cp16(dst, g_WlocH + row * 64 + q * 8);
        cp16(dst + 16384, g_WlocL + row * 64 + q * 8);
    }
    cp_commit();
    cp_wait0();
    __syncthreads();

    const float* pb = memory +
        ((size_t)b * T_ + (size_t)(t0 + tBase + g)) * E_ + cq;
    bool vr[4];
    #pragma unroll
    for (int j = 0; j < 4; ++j) vr[j] = (t0 + tBase + g + 8 * j) < T_;

    // raw A for memory k-step 0 (cols 0..15) — preload early
    float2 f[8];
    #pragma unroll
    for (int i = 0; i < 8; ++i) {
        int ri = ((i >> 2) << 1) | (i & 1);
        const float* p = pb + (size_t)(8 * ri) * E_ + (((i >> 1) & 1) << 3);
        f[i] = vr[ri] ? *(const float2*)p : make_float2(0.f, 0.f);
    }

    float acc[2][8][4];
    #pragma unroll
    for (int m = 0; m < 2; ++m)
        #pragma unroll
        for (int n = 0; n < 8; ++n)
            #pragma unroll
            for (int e = 0; e < 4; ++e) acc[m][n][e] = 0.f;

    uint32_t bRowB[4];
    #pragma unroll
    for (int g4 = 0; g4 < 4; ++g4)
        bRowB[g4] = (uint32_t)(aBase + g4 * 16 + bRowOff) << 7;

    // ---- conv chunk (c=0): A frags from sAw, B in buf0 ----
    {
        // issue B for chunk 1 (memory cols 0..63) into buf1
        #pragma unroll
        for (int it = 0; it < 8; ++it) {
            int idx = it * 128 + tid;
            uint32_t row = (uint32_t)(idx >> 3), q = (uint32_t)(idx & 7);
            uint32_t dst = sb + OFF_B + 32768 +
                           (row << 7) + (((q ^ row) & 7u) << 4);
            cp16(dst, g_WmH + (size_t)row * E_ + q * 8);
            cp16(dst + 16384, g_WmL + (size_t)row * E_ + q * 8);
        }
        cp_commit();
        const uint32_t curB = sb + OFF_B;
        #pragma unroll
        for (int ks = 0; ks < 4; ++ks) {
            uint32_t ah[8], al[8];
            #pragma unroll
            for (int i = 0; i < 8; ++i) {
                int r = tBase + ((i >> 2) << 4) + g + ((i & 1) << 3);
                int j0 = (ks << 4) + cq + (((i >> 1) & 1) << 3);
                float x0 = 0.f, x1 = 0.f;
                if (j0 < 62) {
                    int cj = j0 >= 31;
                    x0 = sAw[cj * 96 + r + (j0 - cj * 31)];
                }
                if (j0 + 1 < 62) {
                    int cj = (j0 + 1) >= 31;
                    x1 = sAw[cj * 96 + r + (j0 + 1 - cj * 31)];
                }
                split2(x0, x1, ah[i], al[i]);
            }
            mma_step(acc, ah, al, curB, ks, bRowB, bCk, rx);
        }
        cp_wait0();
        __syncthreads();
    }

    // ---- memory chunks c = 1..8 ----
    for (int c = 1; c <= 8; ++c) {
        const uint32_t curB = sb + OFF_B + (uint32_t)(c & 1) * 32768;
        if (c < 8) {
            const __half* WH = g_WmH + c * 64;
            const __half* WL = g_WmL + c * 64;
            uint32_t nxtB = sb + OFF_B + (uint32_t)((c + 1) & 1) * 32768;
            #pragma unroll
            for (int it = 0; it < 8; ++it) {
                int idx = it * 128 + tid;
                uint32_t row = (uint32_t)(idx >> 3), q = (uint32_t)(idx & 7);
                uint32_t dst = nxtB + (row << 7) + (((q ^ row) & 7u) << 4);
                cp16(dst, WH + (size_t)row * E_ + q * 8);
                cp16(dst + 16384, WL + (size_t)row * E_ + q * 8);
            }
            cp_commit();
        }
        #pragma unroll
        for (int ks = 0; ks < 4; ++ks) {
            int s = (c - 1) * 4 + ks;            // current memory k-step
            // prefetch raw A for step s+1
            float2 fn[8];
            bool more = s < 31;
            const float* pc = pb + (size_t)(s + 1) * 16;
            #pragma unroll
            for (int i = 0; i < 8; ++i) {
                int ri = ((i >> 2) << 1) | (i & 1);
                const float* p = pc + (size_t)(8 * ri) * E_ +
                                 (((i >> 1) & 1) << 3);
                fn[i] = (more && vr[ri]) ? *(const float2*)p
                                         : make_float2(0.f, 0.f);
            }
            // convert current raw -> frags
            uint32_t ah[8], al[8];
            #pragma unroll
            for (int i = 0; i < 8; ++i)
                split2(f[i].x, f[i].y, ah[i], al[i]);
            mma_step(acc, ah, al, curB, ks, bRowB, bCk, rx);
            #pragma unroll
            for (int i = 0; i < 8; ++i) f[i] = fn[i];
        }
        if (c < 8) cp_wait0();
        __syncthreads();
    }

    // ---- scores: s[t] = sum_a v[a]*tanh(acc + pq[a]) ----
    {
        float s[4] = {0.f, 0.f, 0.f, 0.f};
        #pragma unroll
        for (int m = 0; m < 2; ++m) {
            #pragma unroll
            for (int n = 0; n < 8; ++n) {
                int a0 = aBase + n * 8 + (lid & 3) * 2;
                float v0 = sV[a0], v1 = sV[a0 + 1];
                float q0 = sPQ[a0], q1 = sPQ[a0 + 1];
                s[2 * m]     += v0 * tanhf(acc[m][n][0] + q0)
                              + v1 * tanhf(acc[m][n][1] + q1);
                s[2 * m + 1] += v0 * tanhf(acc[m][n][2] + q0)
                              + v1 * tanhf(acc[m][n][3] + q1);
            }
        }
        #pragma unroll
        for (int off = 1; off < 4; off <<= 1) {
            #pragma unroll
            for (int i = 0; i < 4; ++i)
                s[i] += __shfl_xor_sync(0xffffffffu, s[i], off);
        }
        if ((lid & 3) == 0) {
            int r = tBase + (lid >> 2);
            sSc[warpA * 64 + r]      = s[0];
            sSc[warpA * 64 + r + 8]  = s[1];
            sSc[warpA * 64 + r + 16] = s[2];
            sSc[warpA * 64 + r + 24] = s[3];
        }
    }
    __syncthreads();

    // ---- tile softmax partial ----
    if (tid < TTILE) {
        int gt = t0 + tid;
        float sf = sSc[tid] + sSc[64 + tid];
        bool valid = gt < T_;
        if (valid) g_scores[b * T_ + gt] = sf;
        sFin[tid] = valid ? sf : -1e30f;
    }
    __syncthreads();
    if (wid == 0) {
        float s0 = sFin[lid], s1 = sFin[lid + 32];
        float m = fmaxf(s0, s1);
        #pragma unroll
        for (int off = 16; off; off >>= 1)
            m = fmaxf(m, __shfl_xor_sync(0xffffffffu, m, off));
        float w0 = __expf(s0 - m), w1 = __expf(s1 - m);
        float l = w0 + w1;
        #pragma unroll
        for (int off = 16; off; off >>= 1)
            l += __shfl_xor_sync(0xffffffffu, l, off);
        sW[lid] = w0;
        sW[lid + 32] = w1;
        if (lid == 0) g_mtl[b * NTILES + tile] = make_float2(m, l);
    }
    __syncthreads();

    // ---- ctx partial: cpart[e] = sum_t w[t] * memory[b, t0+t, e] (L2-warm) ----
    {
        const int tmax = min(TTILE, T_ - t0);
        const float* mrow = memory + ((size_t)b * T_ + t0) * E_ + tid * 4;
        float4 acc0 = make_float4(0.f, 0.f, 0.f, 0.f);
        float4 acc1 = make_float4(0.f, 0.f, 0.f, 0.f);
        int t = 0;
        for (; t + 2 <= tmax; t += 2) {
            float w0 = sW[t], w1 = sW[t + 1];
            float4 m0 = *(const float4*)(mrow);
            float4 m1 = *(const float4*)(mrow + E_);
            mrow += 2 * E_;
            acc0.x += w0 * m0.x; acc0.y += w0 * m0.y;
            acc0.z += w0 * m0.z; acc0.w += w0 * m0.w;
            acc1.x += w1 * m1.x; acc1.y += w1 * m1.y;
            acc1.z += w1 * m1.z; acc1.w += w1 * m1.w;
        }
        if (t < tmax) {
            float w0 = sW[t];
            float4 m0 = *(const float4*)(mrow);
            acc0.x += w0 * m0.x; acc0.y += w0 * m0.y;
            acc0.z += w0 * m0.z; acc0.w += w0 * m0.w;
        }
        acc0.x += acc1.x; acc0.y += acc1.y;
        acc0.z += acc1.z; acc0.w += acc1.w;
        *((float4*)(g_cpart + ((size_t)b * NTILES + tile) * E_) + tid) = acc0;
    }
}

// ---------------------------------------------------------------------------
// combine: global softmax over tiles -> context + alignments
// grid (B_, 5): y==0 -> context, y=1..4 -> alignment quarters
// ---------------------------------------------------------------------------
__global__ void combine_kernel(float* __restrict__ ctx_out,
                               float* __restrict__ align_out) {
    __shared__ float fac[NTILES];
    __shared__ float sML[2];
    int b = blockIdx.x, part = blockIdx.y, tid = threadIdx.x;  // 512 threads
    if (tid < NTILES) {
        float2 ml = g_mtl[b * NTILES + tid];
        float M = ml.x;
        #pragma unroll
        for (int off = 16; off; off >>= 1)
            M = fmaxf(M, __shfl_xor_sync(0xffffffffu, M, off));
        float f = __expf(ml.x - M);
        float L = ml.y * f;
        #pragma unroll
        for (int off = 16; off; off >>= 1)
            L += __shfl_xor_sync(0xffffffffu, L, off);
        fac[tid] = f;
        if (tid == 0) { sML[0] = M; sML[1] = L; }
    }
    __syncthreads();
    float M = sML[0];
    float invL = 1.f / sML[1];

    if (part == 0) {
        float s = 0.f;
        #pragma unroll
        for (int i = 0; i < NTILES; ++i)
            s += g_cpart[((size_t)b * NTILES + i) * E_ + tid] * fac[i];
        ctx_out[b * E_ + tid] = s * invL;
    } else {
        int tbeg = (part - 1) * 500;
        for (int t = tbeg + tid; t < tbeg + 500; t += 512)
            align_out[b * T_ + t] = __expf(g_scores[b * T_ + t] - M) * invL;
    }
}

// ---------------------------------------------------------------------------
extern "C" void kernel_launch(void* const* d_in, const int* in_sizes, int n_in,
                              void* d_out, int out_size) {
    const float* query  = (const float*)d_in[0];  // [64,1024]
    const float* memory = (const float*)d_in[1];  // [64,2000,512]
    const float* aw     = (const float*)d_in[2];  // [64,2000,2]
    const float* Wq     = (const float*)d_in[3];  // [128,1024]
    const float* Wm     = (const float*)d_in[4];  // [128,512]
    const float* Wloc   = (const float*)d_in[5];  // [128,2,31]
    const float* v      = (const float*)d_in[6];  // [128]

    float* ctx = (float*)d_out;                   // [64,512]
    float* aligns = ctx + B_ * E_;                // [64,2000]

    cudaFuncSetAttribute(scores_fused_kernel,
                         cudaFuncAttributeMaxDynamicSharedMemorySize, SMEM_TOTAL);

    prep_pq_kernel<<<320, 512>>>(Wm, Wloc, query, Wq);
    scores_fused_kernel<<<dim3(NTILES, B_), 128, SMEM_TOTAL>>>(memory, aw, v);
    combine_kernel<<<dim3(B_, 5), 512>>>(ctx, aligns);
}